// round 6
// baseline (speedup 1.0000x reference)
#include <cuda_runtime.h>
#include <math.h>

#define BB 2
#define SS 2048
#define DD 1024
#define HH 16
#define DH 64
#define MM (BB * SS)   // 4096

// Pre-split tf32 scratch (hi,lo interleaved pairs) + tf32 V.
__device__ unsigned g_xs[MM * DD * 2];           // x split
__device__ unsigned g_ws[4][DD * DD * 2];        // wq,wk,wv,wo split
__device__ unsigned g_qs[BB * HH * SS * DH * 2]; // Q split (pre-scaled 1/8)
__device__ unsigned g_ks[BB * HH * SS * DH * 2]; // K split
__device__ unsigned g_vt[BB * HH * SS * DH];     // V tf32 (single)
__device__ unsigned g_atts[MM * DD * 2];         // attention out split

__device__ __forceinline__ void split_tf32(float x, unsigned& hi, unsigned& lo) {
    unsigned h = __float_as_uint(x) & 0xFFFFE000u;
    hi = h;
    lo = __float_as_uint(x - __uint_as_float(h));
}
__device__ __forceinline__ unsigned f2tf32(float x) {
    unsigned r;
    asm("cvt.rna.tf32.f32 %0, %1;\n" : "=r"(r) : "f"(x));
    return r;
}
__device__ __forceinline__ void mma_tf32(float& c0, float& c1, float& c2, float& c3,
                                         unsigned a0, unsigned a1, unsigned a2, unsigned a3,
                                         unsigned b0, unsigned b1) {
    asm volatile(
        "mma.sync.aligned.m16n8k8.row.col.f32.tf32.tf32.f32 "
        "{%0,%1,%2,%3}, {%4,%5,%6,%7}, {%8,%9}, {%0,%1,%2,%3};\n"
        : "+f"(c0), "+f"(c1), "+f"(c2), "+f"(c3)
        : "r"(a0), "r"(a1), "r"(a2), "r"(a3), "r"(b0), "r"(b1));
}

// ---------------------------------------------------------------------------
// Pre-split x and the 4 weight matrices into tf32 (hi,lo) pairs.
// 2M float4 work items: first 1M = x, next 1M = wq|wk|wv|wo.
// ---------------------------------------------------------------------------
__global__ void __launch_bounds__(256) presplit(const float* __restrict__ x,
                                                const float* __restrict__ wq,
                                                const float* __restrict__ wk,
                                                const float* __restrict__ wv,
                                                const float* __restrict__ wo) {
    unsigned idx = blockIdx.x * 256 + threadIdx.x;   // 0 .. 2M-1
    const float* src;
    unsigned* dst;
    unsigned off;
    if (idx < (1u << 20)) {
        src = x; dst = g_xs; off = idx;
    } else {
        unsigned i2 = idx - (1u << 20);
        unsigned w = i2 >> 18;          // 262144 float4 per W
        off = i2 & 0x3FFFFu;
        src = (w == 0) ? wq : (w == 1) ? wk : (w == 2) ? wv : wo;
        dst = g_ws[w];
    }
    float4 v = *(const float4*)(src + off * 4);
    unsigned h0, l0, h1, l1, h2, l2, h3, l3;
    split_tf32(v.x, h0, l0); split_tf32(v.y, h1, l1);
    split_tf32(v.z, h2, l2); split_tf32(v.w, h3, l3);
    *(uint4*)(dst + off * 8)     = make_uint4(h0, l0, h1, l1);
    *(uint4*)(dst + off * 8 + 4) = make_uint4(h2, l2, h3, l3);
}

// ---------------------------------------------------------------------------
// NT GEMM on pre-split tf32 operands. Block 128x128, 8 warps, 32(m)x64(n)
// warp tile, k-chunk 32. In-loop: LDS.64 + HMMA only.
// mode 0 (z=0/1/2): A=g_xs, W=g_ws[z] -> g_qs (scaled 1/8) / g_ks / g_vt.
// mode 3:           A=g_atts, W=g_ws[3] -> Cext fp32 + bias.
// ---------------------------------------------------------------------------
__global__ void __launch_bounds__(256) gemm_ps(const float* __restrict__ bias,
                                               float* __restrict__ Cext,
                                               int mode) {
    __shared__ unsigned As[128][72];
    __shared__ unsigned Ws[128][72];

    const int t    = threadIdx.x;
    const int lane = t & 31;
    const int warp = t >> 5;
    const int wm   = warp >> 1;
    const int wn   = warp & 1;
    const int g    = lane >> 2;
    const int tg   = lane & 3;

    const int m0 = blockIdx.y * 128;
    const int n0 = blockIdx.x * 128;
    const int z  = blockIdx.z;

    const unsigned* Ap = (mode == 3) ? g_atts : g_xs;
    const unsigned* Wp = (mode == 3) ? g_ws[3] : g_ws[z];

    float c[2][8][4];
#pragma unroll
    for (int mi = 0; mi < 2; mi++)
#pragma unroll
        for (int ni = 0; ni < 8; ni++)
#pragma unroll
            for (int e = 0; e < 4; e++) c[mi][ni][e] = 0.f;

    for (int k0 = 0; k0 < 1024; k0 += 32) {
        __syncthreads();
#pragma unroll
        for (int i = 0; i < 8; i++) {
            int idx = t + i * 256;
            int row = idx >> 4;
            int c4  = (idx & 15) * 4;
            *(uint4*)&As[row][c4] = *(const uint4*)(Ap + (size_t)(m0 + row) * 2048 + k0 * 2 + c4);
            *(uint4*)&Ws[row][c4] = *(const uint4*)(Wp + (size_t)(n0 + row) * 2048 + k0 * 2 + c4);
        }
        __syncthreads();

#pragma unroll
        for (int kb = 0; kb < 4; kb++) {
            const int cA = 2 * (kb * 8 + tg);
            unsigned ah[2][4], al[2][4], bh[8][2], bl[8][2];
#pragma unroll
            for (int mi = 0; mi < 2; mi++) {
                const int rb = wm * 32 + mi * 16;
                uint2 p0 = *(const uint2*)&As[rb + g][cA];
                uint2 p1 = *(const uint2*)&As[rb + g + 8][cA];
                uint2 p2 = *(const uint2*)&As[rb + g][cA + 8];
                uint2 p3 = *(const uint2*)&As[rb + g + 8][cA + 8];
                ah[mi][0] = p0.x; al[mi][0] = p0.y;
                ah[mi][1] = p1.x; al[mi][1] = p1.y;
                ah[mi][2] = p2.x; al[mi][2] = p2.y;
                ah[mi][3] = p3.x; al[mi][3] = p3.y;
            }
#pragma unroll
            for (int ni = 0; ni < 8; ni++) {
                const int nb = wn * 64 + ni * 8;
                uint2 q0 = *(const uint2*)&Ws[nb + g][cA];
                uint2 q1 = *(const uint2*)&Ws[nb + g][cA + 8];
                bh[ni][0] = q0.x; bl[ni][0] = q0.y;
                bh[ni][1] = q1.x; bl[ni][1] = q1.y;
            }
#pragma unroll
            for (int mi = 0; mi < 2; mi++)
#pragma unroll
                for (int ni = 0; ni < 8; ni++) {
                    mma_tf32(c[mi][ni][0], c[mi][ni][1], c[mi][ni][2], c[mi][ni][3],
                             ah[mi][0], ah[mi][1], ah[mi][2], ah[mi][3],
                             bh[ni][0], bh[ni][1]);
                    mma_tf32(c[mi][ni][0], c[mi][ni][1], c[mi][ni][2], c[mi][ni][3],
                             al[mi][0], al[mi][1], al[mi][2], al[mi][3],
                             bh[ni][0], bh[ni][1]);
                    mma_tf32(c[mi][ni][0], c[mi][ni][1], c[mi][ni][2], c[mi][ni][3],
                             ah[mi][0], ah[mi][1], ah[mi][2], ah[mi][3],
                             bl[ni][0], bl[ni][1]);
                }
        }
    }

#pragma unroll
    for (int mi = 0; mi < 2; mi++) {
#pragma unroll
        for (int ni = 0; ni < 8; ni++) {
            int mA = m0 + wm * 32 + mi * 16 + g;
            int mB = mA + 8;
            int n  = n0 + wn * 64 + ni * 8 + 2 * tg;
            if (mode == 3) {
                float bx = bias[n], by = bias[n + 1];
                *(float2*)(Cext + (size_t)mA * 1024 + n) =
                    make_float2(c[mi][ni][0] + bx, c[mi][ni][1] + by);
                *(float2*)(Cext + (size_t)mB * 1024 + n) =
                    make_float2(c[mi][ni][2] + bx, c[mi][ni][3] + by);
            } else {
                int h  = n >> 6;
                int dh = n & 63;
                int bA = mA >> 11, sA = mA & 2047;
                int bC = mB >> 11, sC = mB & 2047;
                size_t eA = (size_t)((bA * HH + h) * SS + sA) * DH + dh;
                size_t eB = (size_t)((bC * HH + h) * SS + sC) * DH + dh;
                if (z == 2) {
                    *(uint2*)(g_vt + eA) = make_uint2(f2tf32(c[mi][ni][0]), f2tf32(c[mi][ni][1]));
                    *(uint2*)(g_vt + eB) = make_uint2(f2tf32(c[mi][ni][2]), f2tf32(c[mi][ni][3]));
                } else {
                    float sc = (z == 0) ? 0.125f : 1.0f;
                    unsigned* dst = (z == 0) ? g_qs : g_ks;
                    unsigned h0, l0, h1, l1;
                    split_tf32(c[mi][ni][0] * sc, h0, l0);
                    split_tf32(c[mi][ni][1] * sc, h1, l1);
                    *(uint4*)(dst + eA * 2) = make_uint4(h0, l0, h1, l1);
                    split_tf32(c[mi][ni][2] * sc, h0, l0);
                    split_tf32(c[mi][ni][3] * sc, h1, l1);
                    *(uint4*)(dst + eB * 2) = make_uint4(h0, l0, h1, l1);
                }
            }
        }
    }
}

// ---------------------------------------------------------------------------
// Flash attention, tf32 mma, pre-split Q/K from gmem, tf32 V.
// Block = 64 query rows, 4 warps (16 rows each), 64-key tiles.
// QK: 3-term split. PV: single tf32 via SMEM P round-trip.
// Writes pre-split output to g_atts.
// ---------------------------------------------------------------------------
__global__ void __launch_bounds__(128) attn_mma() {
    const int b = blockIdx.z;
    const int h = blockIdx.y;
    const int t = threadIdx.x;
    const int warp = t >> 5;
    const int lane = t & 31;
    const int g  = lane >> 2;
    const int tg = lane & 3;
    const int qrow0 = blockIdx.x * 64 + warp * 16;
    const size_t bh = (size_t)(b * HH + h) * SS;

    __shared__ unsigned Ks[64][136];  // split K pairs (stride 136 conflict-free)
    __shared__ unsigned Vs[64][72];   // tf32 V
    __shared__ unsigned Ps[64][68];   // tf32 P

    // Q fragments (hi,lo) straight from pre-split gmem (already scaled 1/8).
    unsigned qh[8][4], ql[8][4];
    {
        const unsigned* Qp = g_qs + (bh + qrow0) * DH * 2;
#pragma unroll
        for (int kb = 0; kb < 8; kb++) {
            uint2 p0 = *(const uint2*)(Qp + (g * DH + kb * 8 + tg) * 2);
            uint2 p1 = *(const uint2*)(Qp + ((g + 8) * DH + kb * 8 + tg) * 2);
            uint2 p2 = *(const uint2*)(Qp + (g * DH + kb * 8 + tg + 4) * 2);
            uint2 p3 = *(const uint2*)(Qp + ((g + 8) * DH + kb * 8 + tg + 4) * 2);
            qh[kb][0] = p0.x; ql[kb][0] = p0.y;
            qh[kb][1] = p1.x; ql[kb][1] = p1.y;
            qh[kb][2] = p2.x; ql[kb][2] = p2.y;
            qh[kb][3] = p3.x; ql[kb][3] = p3.y;
        }
    }

    float o[8][4];
#pragma unroll
    for (int ni = 0; ni < 8; ni++)
#pragma unroll
        for (int e = 0; e < 4; e++) o[ni][e] = 0.f;
    float mi0 = -1e30f, mi8 = -1e30f, li0 = 0.f, li8 = 0.f;

    for (int kt = 0; kt < SS; kt += 64) {
        __syncthreads();
#pragma unroll
        for (int i = 0; i < 16; i++) {   // K: 64 rows x 128 u
            int idx = t + i * 128;
            int r = idx >> 5;
            int c4 = (idx & 31) * 4;
            *(uint4*)&Ks[r][c4] = *(const uint4*)(g_ks + (bh + kt + r) * DH * 2 + c4);
        }
#pragma unroll
        for (int i = 0; i < 8; i++) {    // V: 64 rows x 64 u
            int idx = t + i * 128;
            int r = idx >> 4;
            int c4 = (idx & 15) * 4;
            *(uint4*)&Vs[r][c4] = *(const uint4*)(g_vt + (bh + kt + r) * DH + c4);
        }
        __syncthreads();

        float s[8][4];
#pragma unroll
        for (int ni = 0; ni < 8; ni++)
#pragma unroll
            for (int e = 0; e < 4; e++) s[ni][e] = 0.f;

#pragma unroll
        for (int kb = 0; kb < 8; kb++) {
            const int cK = 2 * (kb * 8 + tg);
#pragma unroll
            for (int ni = 0; ni < 8; ni++) {
                uint2 b0 = *(const uint2*)&Ks[ni * 8 + g][cK];
                uint2 b1 = *(const uint2*)&Ks[ni * 8 + g][cK + 8];
                mma_tf32(s[ni][0], s[ni][1], s[ni][2], s[ni][3],
                         qh[kb][0], qh[kb][1], qh[kb][2], qh[kb][3], b0.x, b1.x);
                mma_tf32(s[ni][0], s[ni][1], s[ni][2], s[ni][3],
                         ql[kb][0], ql[kb][1], ql[kb][2], ql[kb][3], b0.x, b1.x);
                mma_tf32(s[ni][0], s[ni][1], s[ni][2], s[ni][3],
                         qh[kb][0], qh[kb][1], qh[kb][2], qh[kb][3], b0.y, b1.y);
            }
        }

        // Online softmax.
        float t0 = mi0, t8 = mi8;
#pragma unroll
        for (int ni = 0; ni < 8; ni++) {
            t0 = fmaxf(t0, fmaxf(s[ni][0], s[ni][1]));
            t8 = fmaxf(t8, fmaxf(s[ni][2], s[ni][3]));
        }
        t0 = fmaxf(t0, __shfl_xor_sync(0xffffffffu, t0, 1));
        t0 = fmaxf(t0, __shfl_xor_sync(0xffffffffu, t0, 2));
        t8 = fmaxf(t8, __shfl_xor_sync(0xffffffffu, t8, 1));
        t8 = fmaxf(t8, __shfl_xor_sync(0xffffffffu, t8, 2));

        float c0 = __expf(mi0 - t0);
        float c8 = __expf(mi8 - t8);
        mi0 = t0; mi8 = t8;
        li0 *= c0; li8 *= c8;

        float rs0 = 0.f, rs8 = 0.f;
#pragma unroll
        for (int ni = 0; ni < 8; ni++) {
            o[ni][0] *= c0; o[ni][1] *= c0;
            o[ni][2] *= c8; o[ni][3] *= c8;
            float p0 = __expf(s[ni][0] - mi0);
            float p1 = __expf(s[ni][1] - mi0);
            float p2 = __expf(s[ni][2] - mi8);
            float p3 = __expf(s[ni][3] - mi8);
            rs0 += p0 + p1;
            rs8 += p2 + p3;
            Ps[warp * 16 + g][ni * 8 + 2 * tg]         = f2tf32(p0);
            Ps[warp * 16 + g][ni * 8 + 2 * tg + 1]     = f2tf32(p1);
            Ps[warp * 16 + 8 + g][ni * 8 + 2 * tg]     = f2tf32(p2);
            Ps[warp * 16 + 8 + g][ni * 8 + 2 * tg + 1] = f2tf32(p3);
        }
        li0 += rs0; li8 += rs8;
        __syncwarp();

        // O += P * V (single tf32).
#pragma unroll
        for (int kb = 0; kb < 8; kb++) {
            unsigned a0 = Ps[warp * 16 + g][kb * 8 + tg];
            unsigned a1 = Ps[warp * 16 + 8 + g][kb * 8 + tg];
            unsigned a2 = Ps[warp * 16 + g][kb * 8 + tg + 4];
            unsigned a3 = Ps[warp * 16 + 8 + g][kb * 8 + tg + 4];
#pragma unroll
            for (int ni = 0; ni < 8; ni++) {
                mma_tf32(o[ni][0], o[ni][1], o[ni][2], o[ni][3],
                         a0, a1, a2, a3,
                         Vs[kb * 8 + tg][ni * 8 + g], Vs[kb * 8 + tg + 4][ni * 8 + g]);
            }
        }
        __syncwarp();
    }

    li0 += __shfl_xor_sync(0xffffffffu, li0, 1);
    li0 += __shfl_xor_sync(0xffffffffu, li0, 2);
    li8 += __shfl_xor_sync(0xffffffffu, li8, 1);
    li8 += __shfl_xor_sync(0xffffffffu, li8, 2);
    float inv0 = 1.f / li0;
    float inv8 = 1.f / li8;

    // Write pre-split output for the O-projection.
    unsigned* O0 = g_atts + (((size_t)b * SS + qrow0 + g) * DD + h * DH) * 2;
    unsigned* O8 = g_atts + (((size_t)b * SS + qrow0 + 8 + g) * DD + h * DH) * 2;
#pragma unroll
    for (int ni = 0; ni < 8; ni++) {
        unsigned h0, l0, h1, l1;
        split_tf32(o[ni][0] * inv0, h0, l0);
        split_tf32(o[ni][1] * inv0, h1, l1);
        *(uint4*)(O0 + (ni * 8 + 2 * tg) * 2) = make_uint4(h0, l0, h1, l1);
        split_tf32(o[ni][2] * inv8, h0, l0);
        split_tf32(o[ni][3] * inv8, h1, l1);
        *(uint4*)(O8 + (ni * 8 + 2 * tg) * 2) = make_uint4(h0, l0, h1, l1);
    }
}

extern "C" void kernel_launch(void* const* d_in, const int* in_sizes, int n_in,
                              void* d_out, int out_size) {
    const float* x  = (const float*)d_in[0];
    const float* wq = (const float*)d_in[1];
    const float* wk = (const float*)d_in[2];
    const float* wv = (const float*)d_in[3];
    const float* wo = (const float*)d_in[4];
    const float* bo = (const float*)d_in[5];
    float* out = (float*)d_out;

    presplit<<<8192, 256>>>(x, wq, wk, wv, wo);

    dim3 gqkv(DD / 128, MM / 128, 3);
    gemm_ps<<<gqkv, 256>>>(nullptr, nullptr, 0);

    dim3 ga(SS / 64, HH, BB);
    attn_mma<<<ga, 128>>>();

    dim3 go(DD / 128, MM / 128, 1);
    gemm_ps<<<go, 256>>>(bo, out, 3);
}

// round 7
// speedup vs baseline: 1.4838x; 1.4838x over previous
#include <cuda_runtime.h>
#include <math.h>

#define BB 2
#define SS 2048
#define DD 1024
#define HH 16
#define DH 64
#define MM (BB * SS)   // 4096

// Scratch: [B,H,S,Dh] for q,k,v ; [B,S,D] for attention output
__device__ float g_q[BB * HH * SS * DH];
__device__ float g_k[BB * HH * SS * DH];
__device__ float g_v[BB * HH * SS * DH];
__device__ float g_att[BB * SS * DD];

// ---------------------------------------------------------------------------
// tf32 helpers
// ---------------------------------------------------------------------------
__device__ __forceinline__ void split_tf32(float x, unsigned& hi, unsigned& lo) {
    unsigned h = __float_as_uint(x) & 0xFFFFE000u;
    hi = h;
    lo = __float_as_uint(x - __uint_as_float(h));
}
__device__ __forceinline__ unsigned f2tf32(float x) {
    unsigned r;
    asm("cvt.rna.tf32.f32 %0, %1;\n" : "=r"(r) : "f"(x));
    return r;
}
__device__ __forceinline__ void mma_tf32(float& c0, float& c1, float& c2, float& c3,
                                         unsigned a0, unsigned a1, unsigned a2, unsigned a3,
                                         unsigned b0, unsigned b1) {
    asm volatile(
        "mma.sync.aligned.m16n8k8.row.col.f32.tf32.tf32.f32 "
        "{%0,%1,%2,%3}, {%4,%5,%6,%7}, {%8,%9}, {%0,%1,%2,%3};\n"
        : "+f"(c0), "+f"(c1), "+f"(c2), "+f"(c3)
        : "r"(a0), "r"(a1), "r"(a2), "r"(a3), "r"(b0), "r"(b1));
}

// cp.async helpers
__device__ __forceinline__ unsigned smem_u32(const void* p) {
    return (unsigned)__cvta_generic_to_shared(p);
}
__device__ __forceinline__ void cp16(unsigned s, const void* g) {
    asm volatile("cp.async.cg.shared.global [%0], [%1], 16;\n" :: "r"(s), "l"(g));
}
#define CP_COMMIT() asm volatile("cp.async.commit_group;\n" ::: "memory")
#define CP_WAIT1()  asm volatile("cp.async.wait_group 1;\n" ::: "memory")

// ---------------------------------------------------------------------------
// NT GEMM via 3xTF32 tensor cores, cp.async double-buffered tiles.
// C[m,n] = sum_k A[m,k] * W[n,k] (+bias).
// Block tile 128x128, 8 warps, warp tile 32(m)x64(n), k-chunk 32.
// mode 0: fused QKV. A = x, blockIdx.z picks (Wq->g_q, Wk->g_k, Wv->g_v),
//         output in [B,H,S,Dh] layout.
// mode 3: A = g_att, W = W0 (= wo), out -> Cext ([B,S,D]) with bias.
// ---------------------------------------------------------------------------
__global__ void __launch_bounds__(256, 2) gemm_tf32(const float* __restrict__ A,
                                                    const float* __restrict__ W0,
                                                    const float* __restrict__ W1,
                                                    const float* __restrict__ W2,
                                                    const float* __restrict__ bias,
                                                    float* __restrict__ Cext,
                                                    int mode) {
    __shared__ float As[2][128][36];
    __shared__ float Ws[2][128][36];

    const int t    = threadIdx.x;
    const int lane = t & 31;
    const int warp = t >> 5;
    const int wm   = warp >> 1;      // 0..3  (m position)
    const int wn   = warp & 1;       // 0..1  (n position)
    const int g    = lane >> 2;      // groupID 0..7
    const int tg   = lane & 3;       // thread in group 0..3

    const int m0 = blockIdx.y * 128;
    const int n0 = blockIdx.x * 128;
    const int z  = blockIdx.z;

    const float* Asrc = (mode == 3) ? g_att : A;
    const float* W = (mode == 3) ? W0 : (z == 0) ? W0 : (z == 1) ? W1 : W2;
    float* C = (mode == 3) ? Cext : (z == 0) ? g_q : (z == 1) ? g_k : g_v;

    // Per-thread load slice
    const int lrow = t >> 1;          // 0..127
    const int lfc  = (t & 1) * 16;    // 0 or 16 (two float4 per half-row... )
    // Each thread does 4 cp16 per array per chunk: rows lrow, cols lfc..lfc+15? No:
    // use idx scheme: idx = t + i*256; row = idx>>3; fc = (idx&7)*4  (i = 0..3)

    auto load_chunk = [&](int k0, int bufi) {
#pragma unroll
        for (int i = 0; i < 4; i++) {
            int idx = t + i * 256;
            int row = idx >> 3;
            int fc  = (idx & 7) * 4;
            cp16(smem_u32(&As[bufi][row][fc]), Asrc + (size_t)(m0 + row) * 1024 + k0 + fc);
            cp16(smem_u32(&Ws[bufi][row][fc]), W + (size_t)(n0 + row) * 1024 + k0 + fc);
        }
    };

    float c[2][8][4];
#pragma unroll
    for (int mi = 0; mi < 2; mi++)
#pragma unroll
        for (int ni = 0; ni < 8; ni++)
#pragma unroll
            for (int e = 0; e < 4; e++) c[mi][ni][e] = 0.f;

    load_chunk(0, 0);  CP_COMMIT();
    load_chunk(32, 1); CP_COMMIT();

    for (int kc = 0; kc < 32; kc++) {
        CP_WAIT1();
        __syncthreads();
        const int bi = kc & 1;

#pragma unroll
        for (int kk = 0; kk < 4; kk++) {
            const int kb = kk * 8;
            unsigned ah[2][4], al[2][4], bh[8][2], bl[8][2];
#pragma unroll
            for (int mi = 0; mi < 2; mi++) {
                const int rb = wm * 32 + mi * 16;
                split_tf32(As[bi][rb + g][kb + tg],          ah[mi][0], al[mi][0]);
                split_tf32(As[bi][rb + g + 8][kb + tg],      ah[mi][1], al[mi][1]);
                split_tf32(As[bi][rb + g][kb + tg + 4],      ah[mi][2], al[mi][2]);
                split_tf32(As[bi][rb + g + 8][kb + tg + 4],  ah[mi][3], al[mi][3]);
            }
#pragma unroll
            for (int ni = 0; ni < 8; ni++) {
                const int nb = wn * 64 + ni * 8;
                split_tf32(Ws[bi][nb + g][kb + tg],     bh[ni][0], bl[ni][0]);
                split_tf32(Ws[bi][nb + g][kb + tg + 4], bh[ni][1], bl[ni][1]);
            }
#pragma unroll
            for (int mi = 0; mi < 2; mi++)
#pragma unroll
                for (int ni = 0; ni < 8; ni++) {
                    mma_tf32(c[mi][ni][0], c[mi][ni][1], c[mi][ni][2], c[mi][ni][3],
                             ah[mi][0], ah[mi][1], ah[mi][2], ah[mi][3],
                             bh[ni][0], bh[ni][1]);
                    mma_tf32(c[mi][ni][0], c[mi][ni][1], c[mi][ni][2], c[mi][ni][3],
                             al[mi][0], al[mi][1], al[mi][2], al[mi][3],
                             bh[ni][0], bh[ni][1]);
                    mma_tf32(c[mi][ni][0], c[mi][ni][1], c[mi][ni][2], c[mi][ni][3],
                             ah[mi][0], ah[mi][1], ah[mi][2], ah[mi][3],
                             bl[ni][0], bl[ni][1]);
                }
        }

        __syncthreads();
        if (kc < 30) load_chunk((kc + 2) * 32, bi);
        CP_COMMIT();
    }

    // Epilogue: each c fragment element pair (c0,c1)/(c2,c3) is 2 contiguous n.
#pragma unroll
    for (int mi = 0; mi < 2; mi++) {
#pragma unroll
        for (int ni = 0; ni < 8; ni++) {
            int mA = m0 + wm * 32 + mi * 16 + g;
            int mB = mA + 8;
            int n  = n0 + wn * 64 + ni * 8 + 2 * tg;
            if (mode == 3) {
                float bx = bias[n], by = bias[n + 1];
                *(float2*)(C + (size_t)mA * 1024 + n) =
                    make_float2(c[mi][ni][0] + bx, c[mi][ni][1] + by);
                *(float2*)(C + (size_t)mB * 1024 + n) =
                    make_float2(c[mi][ni][2] + bx, c[mi][ni][3] + by);
            } else {
                int h  = n >> 6;
                int dh = n & 63;
                {
                    int b = mA >> 11, s = mA & 2047;
                    *(float2*)(C + (size_t)((b * HH + h) * SS + s) * DH + dh) =
                        make_float2(c[mi][ni][0], c[mi][ni][1]);
                }
                {
                    int b = mB >> 11, s = mB & 2047;
                    *(float2*)(C + (size_t)((b * HH + h) * SS + s) * DH + dh) =
                        make_float2(c[mi][ni][2], c[mi][ni][3]);
                }
            }
        }
    }
}

// ---------------------------------------------------------------------------
// Flash attention via tensor cores, cp.async double-buffered K/V tiles.
// Block = 64 query rows, 4 warps (16 rows each), 64-key tiles through SMEM.
// QK^T: 3xTF32 split. P*V: single tf32 (RN conversion at use).
// Reads g_q/g_k/g_v [B,H,S,Dh]; writes g_att [B,S,D].
// ---------------------------------------------------------------------------
__global__ void __launch_bounds__(128, 2) attn_mma() {
    const int b = blockIdx.z;
    const int h = blockIdx.y;
    const int t = threadIdx.x;
    const int warp = t >> 5;
    const int lane = t & 31;
    const int g  = lane >> 2;   // 0..7
    const int tg = lane & 3;    // 0..3
    const int qrow0 = blockIdx.x * 64 + warp * 16;
    const size_t bh = (size_t)(b * HH + h) * SS;

    __shared__ float    Ks[2][64][68];   // fp32 K (stride 68: 4g+tg conflict-free)
    __shared__ float    Vs[2][64][72];   // fp32 V (stride 72: 8tg+g conflict-free)
    __shared__ unsigned Ps[64][68];      // tf32 P (per-warp 16-row slabs)

    auto load_kv = [&](int kt, int bufi) {
#pragma unroll
        for (int i = 0; i < 8; i++) {
            int idx = t + i * 128;
            int r = idx >> 4;
            int c = (idx & 15) * 4;
            cp16(smem_u32(&Ks[bufi][r][c]), g_k + (bh + kt + r) * DH + c);
            cp16(smem_u32(&Vs[bufi][r][c]), g_v + (bh + kt + r) * DH + c);
        }
    };

    // Q fragments for this warp's 16 rows, pre-scaled and split (persist).
    unsigned qh[8][4], ql[8][4];
    {
        const float* Q = g_q + (bh + qrow0) * DH;
#pragma unroll
        for (int kb = 0; kb < 8; kb++) {
            float a0 = Q[g * DH + kb * 8 + tg] * 0.125f;
            float a1 = Q[(g + 8) * DH + kb * 8 + tg] * 0.125f;
            float a2 = Q[g * DH + kb * 8 + tg + 4] * 0.125f;
            float a3 = Q[(g + 8) * DH + kb * 8 + tg + 4] * 0.125f;
            split_tf32(a0, qh[kb][0], ql[kb][0]);
            split_tf32(a1, qh[kb][1], ql[kb][1]);
            split_tf32(a2, qh[kb][2], ql[kb][2]);
            split_tf32(a3, qh[kb][3], ql[kb][3]);
        }
    }

    float o[8][4];
#pragma unroll
    for (int ni = 0; ni < 8; ni++)
#pragma unroll
        for (int e = 0; e < 4; e++) o[ni][e] = 0.f;
    float mi0 = -1e30f, mi8 = -1e30f, li0 = 0.f, li8 = 0.f;

    load_kv(0, 0);  CP_COMMIT();
    load_kv(64, 1); CP_COMMIT();

    for (int it = 0; it < 32; it++) {
        CP_WAIT1();
        __syncthreads();
        const int bi = it & 1;

        // S = Q * K^T (3x split), warp computes 16x64 scores.
        float s[8][4];
#pragma unroll
        for (int ni = 0; ni < 8; ni++)
#pragma unroll
            for (int e = 0; e < 4; e++) s[ni][e] = 0.f;

#pragma unroll
        for (int kb = 0; kb < 8; kb++) {
#pragma unroll
            for (int ni = 0; ni < 8; ni++) {
                unsigned b0h, b0l, b1h, b1l;
                split_tf32(Ks[bi][ni * 8 + g][kb * 8 + tg],     b0h, b0l);
                split_tf32(Ks[bi][ni * 8 + g][kb * 8 + tg + 4], b1h, b1l);
                mma_tf32(s[ni][0], s[ni][1], s[ni][2], s[ni][3],
                         qh[kb][0], qh[kb][1], qh[kb][2], qh[kb][3], b0h, b1h);
                mma_tf32(s[ni][0], s[ni][1], s[ni][2], s[ni][3],
                         ql[kb][0], ql[kb][1], ql[kb][2], ql[kb][3], b0h, b1h);
                mma_tf32(s[ni][0], s[ni][1], s[ni][2], s[ni][3],
                         qh[kb][0], qh[kb][1], qh[kb][2], qh[kb][3], b0l, b1l);
            }
        }

        // Online softmax. Rows: g (elements 0,1) and g+8 (elements 2,3).
        float t0 = mi0, t8 = mi8;
#pragma unroll
        for (int ni = 0; ni < 8; ni++) {
            t0 = fmaxf(t0, fmaxf(s[ni][0], s[ni][1]));
            t8 = fmaxf(t8, fmaxf(s[ni][2], s[ni][3]));
        }
        t0 = fmaxf(t0, __shfl_xor_sync(0xffffffffu, t0, 1));
        t0 = fmaxf(t0, __shfl_xor_sync(0xffffffffu, t0, 2));
        t8 = fmaxf(t8, __shfl_xor_sync(0xffffffffu, t8, 1));
        t8 = fmaxf(t8, __shfl_xor_sync(0xffffffffu, t8, 2));

        float c0 = __expf(mi0 - t0);
        float c8 = __expf(mi8 - t8);
        mi0 = t0; mi8 = t8;
        li0 *= c0; li8 *= c8;

        float rs0 = 0.f, rs8 = 0.f;
#pragma unroll
        for (int ni = 0; ni < 8; ni++) {
            o[ni][0] *= c0; o[ni][1] *= c0;
            o[ni][2] *= c8; o[ni][3] *= c8;
            float p0 = __expf(s[ni][0] - mi0);
            float p1 = __expf(s[ni][1] - mi0);
            float p2 = __expf(s[ni][2] - mi8);
            float p3 = __expf(s[ni][3] - mi8);
            rs0 += p0 + p1;
            rs8 += p2 + p3;
            Ps[warp * 16 + g][ni * 8 + 2 * tg]         = f2tf32(p0);
            Ps[warp * 16 + g][ni * 8 + 2 * tg + 1]     = f2tf32(p1);
            Ps[warp * 16 + 8 + g][ni * 8 + 2 * tg]     = f2tf32(p2);
            Ps[warp * 16 + 8 + g][ni * 8 + 2 * tg + 1] = f2tf32(p3);
        }
        li0 += rs0; li8 += rs8;
        __syncwarp();

        // O += P * V (single tf32; V converted RNA at use).
#pragma unroll
        for (int kb = 0; kb < 8; kb++) {
            unsigned a0 = Ps[warp * 16 + g][kb * 8 + tg];
            unsigned a1 = Ps[warp * 16 + 8 + g][kb * 8 + tg];
            unsigned a2 = Ps[warp * 16 + g][kb * 8 + tg + 4];
            unsigned a3 = Ps[warp * 16 + 8 + g][kb * 8 + tg + 4];
#pragma unroll
            for (int ni = 0; ni < 8; ni++) {
                mma_tf32(o[ni][0], o[ni][1], o[ni][2], o[ni][3],
                         a0, a1, a2, a3,
                         f2tf32(Vs[bi][kb * 8 + tg][ni * 8 + g]),
                         f2tf32(Vs[bi][kb * 8 + tg + 4][ni * 8 + g]));
            }
        }

        __syncthreads();
        if (it < 30) load_kv((it + 2) * 64, bi);
        CP_COMMIT();
    }

    li0 += __shfl_xor_sync(0xffffffffu, li0, 1);
    li0 += __shfl_xor_sync(0xffffffffu, li0, 2);
    li8 += __shfl_xor_sync(0xffffffffu, li8, 1);
    li8 += __shfl_xor_sync(0xffffffffu, li8, 2);
    float inv0 = 1.f / li0;
    float inv8 = 1.f / li8;

    float* O0 = g_att + ((size_t)b * SS + qrow0 + g) * DD + h * DH;
    float* O8 = g_att + ((size_t)b * SS + qrow0 + 8 + g) * DD + h * DH;
#pragma unroll
    for (int ni = 0; ni < 8; ni++) {
        *(float2*)(O0 + ni * 8 + 2 * tg) = make_float2(o[ni][0] * inv0, o[ni][1] * inv0);
        *(float2*)(O8 + ni * 8 + 2 * tg) = make_float2(o[ni][2] * inv8, o[ni][3] * inv8);
    }
}

extern "C" void kernel_launch(void* const* d_in, const int* in_sizes, int n_in,
                              void* d_out, int out_size) {
    const float* x  = (const float*)d_in[0];
    const float* wq = (const float*)d_in[1];
    const float* wk = (const float*)d_in[2];
    const float* wv = (const float*)d_in[3];
    const float* wo = (const float*)d_in[4];
    const float* bo = (const float*)d_in[5];
    float* out = (float*)d_out;

    dim3 gqkv(DD / 128, MM / 128, 3);   // (8, 32, 3) fused Q/K/V projections
    gemm_tf32<<<gqkv, 256>>>(x, wq, wk, wv, nullptr, nullptr, 0);

    dim3 ga(SS / 64, HH, BB);           // (32, 16, 2)
    attn_mma<<<ga, 128>>>();

    dim3 go(DD / 128, MM / 128, 1);
    gemm_tf32<<<go, 256>>>(nullptr, wo, nullptr, nullptr, bo, out, 3);
}

// round 8
// speedup vs baseline: 1.8861x; 1.2711x over previous
#include <cuda_runtime.h>
#include <math.h>

#define BB 2
#define SS 2048
#define DD 1024
#define HH 16
#define DH 64
#define MM (BB * SS)   // 4096

// Scratch: [B,H,S,Dh] for q,k,v ; [B,S,D] for attention output
__device__ float g_q[BB * HH * SS * DH];
__device__ float g_k[BB * HH * SS * DH];
__device__ float g_v[BB * HH * SS * DH];
__device__ float g_att[BB * SS * DD];

// ---------------------------------------------------------------------------
// tf32 helpers. 2-term split: hi = RN_tf32(x) (round-to-nearest halves |lo|
// vs truncation), lo = x - hi (raw fp32 bits; HW truncation of lo's low bits
// adds only ~2^-23 relative). Products kept: hi*hi + lo*hi.
// ---------------------------------------------------------------------------
__device__ __forceinline__ void split_tf32(float x, unsigned& hi, unsigned& lo) {
    unsigned h;
    asm("cvt.rna.tf32.f32 %0, %1;\n" : "=r"(h) : "f"(x));
    hi = h;
    lo = __float_as_uint(x - __uint_as_float(h));
}
__device__ __forceinline__ unsigned f2tf32(float x) {
    unsigned r;
    asm("cvt.rna.tf32.f32 %0, %1;\n" : "=r"(r) : "f"(x));
    return r;
}
__device__ __forceinline__ void mma_tf32(float& c0, float& c1, float& c2, float& c3,
                                         unsigned a0, unsigned a1, unsigned a2, unsigned a3,
                                         unsigned b0, unsigned b1) {
    asm volatile(
        "mma.sync.aligned.m16n8k8.row.col.f32.tf32.tf32.f32 "
        "{%0,%1,%2,%3}, {%4,%5,%6,%7}, {%8,%9}, {%0,%1,%2,%3};\n"
        : "+f"(c0), "+f"(c1), "+f"(c2), "+f"(c3)
        : "r"(a0), "r"(a1), "r"(a2), "r"(a3), "r"(b0), "r"(b1));
}

// cp.async helpers
__device__ __forceinline__ unsigned smem_u32(const void* p) {
    return (unsigned)__cvta_generic_to_shared(p);
}
__device__ __forceinline__ void cp16(unsigned s, const void* g) {
    asm volatile("cp.async.cg.shared.global [%0], [%1], 16;\n" :: "r"(s), "l"(g));
}
#define CP_COMMIT() asm volatile("cp.async.commit_group;\n" ::: "memory")
#define CP_WAIT1()  asm volatile("cp.async.wait_group 1;\n" ::: "memory")

// ---------------------------------------------------------------------------
// NT GEMM via 2-term tf32 tensor cores, cp.async double-buffered tiles.
// C[m,n] = sum_k A[m,k] * W[n,k] (+bias).
// Block tile 128x128, 8 warps, warp tile 32(m)x64(n), k-chunk 32.
// mode 0: fused QKV. A = x, blockIdx.z picks (Wq->g_q, Wk->g_k, Wv->g_v),
//         output in [B,H,S,Dh] layout.
// mode 3: A = g_att, W = W0 (= wo), out -> Cext ([B,S,D]) with bias.
// ---------------------------------------------------------------------------
__global__ void __launch_bounds__(256, 2) gemm_tf32(const float* __restrict__ A,
                                                    const float* __restrict__ W0,
                                                    const float* __restrict__ W1,
                                                    const float* __restrict__ W2,
                                                    const float* __restrict__ bias,
                                                    float* __restrict__ Cext,
                                                    int mode) {
    __shared__ float As[2][128][36];
    __shared__ float Ws[2][128][36];

    const int t    = threadIdx.x;
    const int lane = t & 31;
    const int warp = t >> 5;
    const int wm   = warp >> 1;      // 0..3  (m position)
    const int wn   = warp & 1;       // 0..1  (n position)
    const int g    = lane >> 2;      // groupID 0..7
    const int tg   = lane & 3;       // thread in group 0..3

    const int m0 = blockIdx.y * 128;
    const int n0 = blockIdx.x * 128;
    const int z  = blockIdx.z;

    const float* Asrc = (mode == 3) ? g_att : A;
    const float* W = (mode == 3) ? W0 : (z == 0) ? W0 : (z == 1) ? W1 : W2;
    float* C = (mode == 3) ? Cext : (z == 0) ? g_q : (z == 1) ? g_k : g_v;

    auto load_chunk = [&](int k0, int bufi) {
#pragma unroll
        for (int i = 0; i < 4; i++) {
            int idx = t + i * 256;
            int row = idx >> 3;
            int fc  = (idx & 7) * 4;
            cp16(smem_u32(&As[bufi][row][fc]), Asrc + (size_t)(m0 + row) * 1024 + k0 + fc);
            cp16(smem_u32(&Ws[bufi][row][fc]), W + (size_t)(n0 + row) * 1024 + k0 + fc);
        }
    };

    float c[2][8][4];
#pragma unroll
    for (int mi = 0; mi < 2; mi++)
#pragma unroll
        for (int ni = 0; ni < 8; ni++)
#pragma unroll
            for (int e = 0; e < 4; e++) c[mi][ni][e] = 0.f;

    load_chunk(0, 0);  CP_COMMIT();
    load_chunk(32, 1); CP_COMMIT();

    for (int kc = 0; kc < 32; kc++) {
        CP_WAIT1();
        __syncthreads();
        const int bi = kc & 1;

#pragma unroll
        for (int kk = 0; kk < 4; kk++) {
            const int kb = kk * 8;
            unsigned ah[2][4], al[2][4], bh[8][2];
#pragma unroll
            for (int mi = 0; mi < 2; mi++) {
                const int rb = wm * 32 + mi * 16;
                split_tf32(As[bi][rb + g][kb + tg],          ah[mi][0], al[mi][0]);
                split_tf32(As[bi][rb + g + 8][kb + tg],      ah[mi][1], al[mi][1]);
                split_tf32(As[bi][rb + g][kb + tg + 4],      ah[mi][2], al[mi][2]);
                split_tf32(As[bi][rb + g + 8][kb + tg + 4],  ah[mi][3], al[mi][3]);
            }
#pragma unroll
            for (int ni = 0; ni < 8; ni++) {
                const int nb = wn * 64 + ni * 8;
                bh[ni][0] = f2tf32(Ws[bi][nb + g][kb + tg]);
                bh[ni][1] = f2tf32(Ws[bi][nb + g][kb + tg + 4]);
            }
#pragma unroll
            for (int mi = 0; mi < 2; mi++)
#pragma unroll
                for (int ni = 0; ni < 8; ni++) {
                    mma_tf32(c[mi][ni][0], c[mi][ni][1], c[mi][ni][2], c[mi][ni][3],
                             ah[mi][0], ah[mi][1], ah[mi][2], ah[mi][3],
                             bh[ni][0], bh[ni][1]);
                    mma_tf32(c[mi][ni][0], c[mi][ni][1], c[mi][ni][2], c[mi][ni][3],
                             al[mi][0], al[mi][1], al[mi][2], al[mi][3],
                             bh[ni][0], bh[ni][1]);
                }
        }

        __syncthreads();
        if (kc < 30) load_chunk((kc + 2) * 32, bi);
        CP_COMMIT();
    }

    // Epilogue: each c fragment element pair (c0,c1)/(c2,c3) is 2 contiguous n.
#pragma unroll
    for (int mi = 0; mi < 2; mi++) {
#pragma unroll
        for (int ni = 0; ni < 8; ni++) {
            int mA = m0 + wm * 32 + mi * 16 + g;
            int mB = mA + 8;
            int n  = n0 + wn * 64 + ni * 8 + 2 * tg;
            if (mode == 3) {
                float bx = bias[n], by = bias[n + 1];
                *(float2*)(C + (size_t)mA * 1024 + n) =
                    make_float2(c[mi][ni][0] + bx, c[mi][ni][1] + by);
                *(float2*)(C + (size_t)mB * 1024 + n) =
                    make_float2(c[mi][ni][2] + bx, c[mi][ni][3] + by);
            } else {
                int h  = n >> 6;
                int dh = n & 63;
                {
                    int b = mA >> 11, s = mA & 2047;
                    *(float2*)(C + (size_t)((b * HH + h) * SS + s) * DH + dh) =
                        make_float2(c[mi][ni][0], c[mi][ni][1]);
                }
                {
                    int b = mB >> 11, s = mB & 2047;
                    *(float2*)(C + (size_t)((b * HH + h) * SS + s) * DH + dh) =
                        make_float2(c[mi][ni][2], c[mi][ni][3]);
                }
            }
        }
    }
}

// ---------------------------------------------------------------------------
// Flash attention via tensor cores, cp.async double-buffered K/V tiles.
// Block = 64 query rows, 4 warps (16 rows each), 64-key tiles through SMEM.
// QK^T: 2-term tf32 split. P*V: single tf32 (RN conversion at use).
// Reads g_q/g_k/g_v [B,H,S,Dh]; writes g_att [B,S,D].
// ---------------------------------------------------------------------------
__global__ void __launch_bounds__(128, 2) attn_mma() {
    const int b = blockIdx.z;
    const int h = blockIdx.y;
    const int t = threadIdx.x;
    const int warp = t >> 5;
    const int lane = t & 31;
    const int g  = lane >> 2;   // 0..7
    const int tg = lane & 3;    // 0..3
    const int qrow0 = blockIdx.x * 64 + warp * 16;
    const size_t bh = (size_t)(b * HH + h) * SS;

    __shared__ float    Ks[2][64][68];   // fp32 K (stride 68: 4g+tg conflict-free)
    __shared__ float    Vs[2][64][72];   // fp32 V (stride 72: 8tg+g conflict-free)
    __shared__ unsigned Ps[64][68];      // tf32 P (per-warp 16-row slabs)

    auto load_kv = [&](int kt, int bufi) {
#pragma unroll
        for (int i = 0; i < 8; i++) {
            int idx = t + i * 128;
            int r = idx >> 4;
            int c = (idx & 15) * 4;
            cp16(smem_u32(&Ks[bufi][r][c]), g_k + (bh + kt + r) * DH + c);
            cp16(smem_u32(&Vs[bufi][r][c]), g_v + (bh + kt + r) * DH + c);
        }
    };

    // Q fragments for this warp's 16 rows, pre-scaled and split (persist).
    unsigned qh[8][4], ql[8][4];
    {
        const float* Q = g_q + (bh + qrow0) * DH;
#pragma unroll
        for (int kb = 0; kb < 8; kb++) {
            float a0 = Q[g * DH + kb * 8 + tg] * 0.125f;
            float a1 = Q[(g + 8) * DH + kb * 8 + tg] * 0.125f;
            float a2 = Q[g * DH + kb * 8 + tg + 4] * 0.125f;
            float a3 = Q[(g + 8) * DH + kb * 8 + tg + 4] * 0.125f;
            split_tf32(a0, qh[kb][0], ql[kb][0]);
            split_tf32(a1, qh[kb][1], ql[kb][1]);
            split_tf32(a2, qh[kb][2], ql[kb][2]);
            split_tf32(a3, qh[kb][3], ql[kb][3]);
        }
    }

    float o[8][4];
#pragma unroll
    for (int ni = 0; ni < 8; ni++)
#pragma unroll
        for (int e = 0; e < 4; e++) o[ni][e] = 0.f;
    float mi0 = -1e30f, mi8 = -1e30f, li0 = 0.f, li8 = 0.f;

    load_kv(0, 0);  CP_COMMIT();
    load_kv(64, 1); CP_COMMIT();

    for (int it = 0; it < 32; it++) {
        CP_WAIT1();
        __syncthreads();
        const int bi = it & 1;

        // S = Q * K^T (2-term), warp computes 16x64 scores.
        float s[8][4];
#pragma unroll
        for (int ni = 0; ni < 8; ni++)
#pragma unroll
            for (int e = 0; e < 4; e++) s[ni][e] = 0.f;

#pragma unroll
        for (int kb = 0; kb < 8; kb++) {
#pragma unroll
            for (int ni = 0; ni < 8; ni++) {
                unsigned b0h = f2tf32(Ks[bi][ni * 8 + g][kb * 8 + tg]);
                unsigned b1h = f2tf32(Ks[bi][ni * 8 + g][kb * 8 + tg + 4]);
                mma_tf32(s[ni][0], s[ni][1], s[ni][2], s[ni][3],
                         qh[kb][0], qh[kb][1], qh[kb][2], qh[kb][3], b0h, b1h);
                mma_tf32(s[ni][0], s[ni][1], s[ni][2], s[ni][3],
                         ql[kb][0], ql[kb][1], ql[kb][2], ql[kb][3], b0h, b1h);
            }
        }

        // Online softmax. Rows: g (elements 0,1) and g+8 (elements 2,3).
        float t0 = mi0, t8 = mi8;
#pragma unroll
        for (int ni = 0; ni < 8; ni++) {
            t0 = fmaxf(t0, fmaxf(s[ni][0], s[ni][1]));
            t8 = fmaxf(t8, fmaxf(s[ni][2], s[ni][3]));
        }
        t0 = fmaxf(t0, __shfl_xor_sync(0xffffffffu, t0, 1));
        t0 = fmaxf(t0, __shfl_xor_sync(0xffffffffu, t0, 2));
        t8 = fmaxf(t8, __shfl_xor_sync(0xffffffffu, t8, 1));
        t8 = fmaxf(t8, __shfl_xor_sync(0xffffffffu, t8, 2));

        float c0 = __expf(mi0 - t0);
        float c8 = __expf(mi8 - t8);
        mi0 = t0; mi8 = t8;
        li0 *= c0; li8 *= c8;

        float rs0 = 0.f, rs8 = 0.f;
#pragma unroll
        for (int ni = 0; ni < 8; ni++) {
            o[ni][0] *= c0; o[ni][1] *= c0;
            o[ni][2] *= c8; o[ni][3] *= c8;
            float p0 = __expf(s[ni][0] - mi0);
            float p1 = __expf(s[ni][1] - mi0);
            float p2 = __expf(s[ni][2] - mi8);
            float p3 = __expf(s[ni][3] - mi8);
            rs0 += p0 + p1;
            rs8 += p2 + p3;
            Ps[warp * 16 + g][ni * 8 + 2 * tg]         = f2tf32(p0);
            Ps[warp * 16 + g][ni * 8 + 2 * tg + 1]     = f2tf32(p1);
            Ps[warp * 16 + 8 + g][ni * 8 + 2 * tg]     = f2tf32(p2);
            Ps[warp * 16 + 8 + g][ni * 8 + 2 * tg + 1] = f2tf32(p3);
        }
        li0 += rs0; li8 += rs8;
        __syncwarp();

        // O += P * V (single tf32; V converted RNA at use).
#pragma unroll
        for (int kb = 0; kb < 8; kb++) {
            unsigned a0 = Ps[warp * 16 + g][kb * 8 + tg];
            unsigned a1 = Ps[warp * 16 + 8 + g][kb * 8 + tg];
            unsigned a2 = Ps[warp * 16 + g][kb * 8 + tg + 4];
            unsigned a3 = Ps[warp * 16 + 8 + g][kb * 8 + tg + 4];
#pragma unroll
            for (int ni = 0; ni < 8; ni++) {
                mma_tf32(o[ni][0], o[ni][1], o[ni][2], o[ni][3],
                         a0, a1, a2, a3,
                         f2tf32(Vs[bi][kb * 8 + tg][ni * 8 + g]),
                         f2tf32(Vs[bi][kb * 8 + tg + 4][ni * 8 + g]));
            }
        }

        __syncthreads();
        if (it < 30) load_kv((it + 2) * 64, bi);
        CP_COMMIT();
    }

    li0 += __shfl_xor_sync(0xffffffffu, li0, 1);
    li0 += __shfl_xor_sync(0xffffffffu, li0, 2);
    li8 += __shfl_xor_sync(0xffffffffu, li8, 1);
    li8 += __shfl_xor_sync(0xffffffffu, li8, 2);
    float inv0 = 1.f / li0;
    float inv8 = 1.f / li8;

    float* O0 = g_att + ((size_t)b * SS + qrow0 + g) * DD + h * DH;
    float* O8 = g_att + ((size_t)b * SS + qrow0 + 8 + g) * DD + h * DH;
#pragma unroll
    for (int ni = 0; ni < 8; ni++) {
        *(float2*)(O0 + ni * 8 + 2 * tg) = make_float2(o[ni][0] * inv0, o[ni][1] * inv0);
        *(float2*)(O8 + ni * 8 + 2 * tg) = make_float2(o[ni][2] * inv8, o[ni][3] * inv8);
    }
}

extern "C" void kernel_launch(void* const* d_in, const int* in_sizes, int n_in,
                              void* d_out, int out_size) {
    const float* x  = (const float*)d_in[0];
    const float* wq = (const float*)d_in[1];
    const float* wk = (const float*)d_in[2];
    const float* wv = (const float*)d_in[3];
    const float* wo = (const float*)d_in[4];
    const float* bo = (const float*)d_in[5];
    float* out = (float*)d_out;

    dim3 gqkv(DD / 128, MM / 128, 3);   // (8, 32, 3) fused Q/K/V projections
    gemm_tf32<<<gqkv, 256>>>(x, wq, wk, wv, nullptr, nullptr, 0);

    dim3 ga(SS / 64, HH, BB);           // (32, 16, 2)
    attn_mma<<<ga, 128>>>();

    dim3 go(DD / 128, MM / 128, 1);
    gemm_tf32<<<go, 256>>>(nullptr, wo, nullptr, nullptr, bo, out, 3);
}

// round 9
// speedup vs baseline: 2.2610x; 1.1988x over previous
#include <cuda_runtime.h>
#include <math.h>

#define BB 2
#define SS 2048
#define DD 1024
#define HH 16
#define DH 64
#define MM (BB * SS)   // 4096

// Scratch: [B,H,S,Dh] for q,k,v ; [B,S,D] for attention output
__device__ float g_q[BB * HH * SS * DH];
__device__ float g_k[BB * HH * SS * DH];
__device__ float g_v[BB * HH * SS * DH];
__device__ float g_att[BB * SS * DD];

// ---------------------------------------------------------------------------
// tf32 helpers. 2-term split: hi = RN_tf32(x), lo = x - hi (exact).
// Products kept: hi*bh + lo*bh == x*bh; error only from B conversion.
// ---------------------------------------------------------------------------
__device__ __forceinline__ void split_tf32(float x, unsigned& hi, unsigned& lo) {
    unsigned h;
    asm("cvt.rna.tf32.f32 %0, %1;\n" : "=r"(h) : "f"(x));
    hi = h;
    lo = __float_as_uint(x - __uint_as_float(h));
}
__device__ __forceinline__ unsigned f2tf32(float x) {
    unsigned r;
    asm("cvt.rna.tf32.f32 %0, %1;\n" : "=r"(r) : "f"(x));
    return r;
}
__device__ __forceinline__ unsigned packbf(float x0, float x1) {  // lo=x0, hi=x1
    unsigned r;
    asm("cvt.rn.bf16x2.f32 %0, %1, %2;" : "=r"(r) : "f"(x1), "f"(x0));
    return r;
}
__device__ __forceinline__ void mma_tf32(float& c0, float& c1, float& c2, float& c3,
                                         unsigned a0, unsigned a1, unsigned a2, unsigned a3,
                                         unsigned b0, unsigned b1) {
    asm volatile(
        "mma.sync.aligned.m16n8k8.row.col.f32.tf32.tf32.f32 "
        "{%0,%1,%2,%3}, {%4,%5,%6,%7}, {%8,%9}, {%0,%1,%2,%3};\n"
        : "+f"(c0), "+f"(c1), "+f"(c2), "+f"(c3)
        : "r"(a0), "r"(a1), "r"(a2), "r"(a3), "r"(b0), "r"(b1));
}
__device__ __forceinline__ void mma_bf16(float& c0, float& c1, float& c2, float& c3,
                                         unsigned a0, unsigned a1, unsigned a2, unsigned a3,
                                         unsigned b0, unsigned b1) {
    asm volatile(
        "mma.sync.aligned.m16n8k16.row.col.f32.bf16.bf16.f32 "
        "{%0,%1,%2,%3}, {%4,%5,%6,%7}, {%8,%9}, {%0,%1,%2,%3};\n"
        : "+f"(c0), "+f"(c1), "+f"(c2), "+f"(c3)
        : "r"(a0), "r"(a1), "r"(a2), "r"(a3), "r"(b0), "r"(b1));
}

// cp.async helpers
__device__ __forceinline__ unsigned smem_u32(const void* p) {
    return (unsigned)__cvta_generic_to_shared(p);
}
__device__ __forceinline__ void cp16(unsigned s, const void* g) {
    asm volatile("cp.async.cg.shared.global [%0], [%1], 16;\n" :: "r"(s), "l"(g));
}
#define CP_COMMIT() asm volatile("cp.async.commit_group;\n" ::: "memory")
#define CP_WAIT1()  asm volatile("cp.async.wait_group 1;\n" ::: "memory")

// ---------------------------------------------------------------------------
// NT GEMM via 2-term tf32 tensor cores, cp.async double-buffered tiles.
// C[m,n] = sum_k A[m,k] * W[n,k] (+bias).
// Block tile 128x128, 8 warps, warp tile 32(m)x64(n), k-chunk 32.
// mode 0: fused QKV. A = x, blockIdx.z picks (Wq->g_q, Wk->g_k, Wv->g_v),
//         output in [B,H,S,Dh] layout.
// mode 3: A = g_att, W = W0 (= wo), out -> Cext ([B,S,D]) with bias.
// ---------------------------------------------------------------------------
__global__ void __launch_bounds__(256, 2) gemm_tf32(const float* __restrict__ A,
                                                    const float* __restrict__ W0,
                                                    const float* __restrict__ W1,
                                                    const float* __restrict__ W2,
                                                    const float* __restrict__ bias,
                                                    float* __restrict__ Cext,
                                                    int mode) {
    __shared__ float As[2][128][36];
    __shared__ float Ws[2][128][36];

    const int t    = threadIdx.x;
    const int lane = t & 31;
    const int warp = t >> 5;
    const int wm   = warp >> 1;      // 0..3  (m position)
    const int wn   = warp & 1;       // 0..1  (n position)
    const int g    = lane >> 2;      // groupID 0..7
    const int tg   = lane & 3;       // thread in group 0..3

    const int m0 = blockIdx.y * 128;
    const int n0 = blockIdx.x * 128;
    const int z  = blockIdx.z;

    const float* Asrc = (mode == 3) ? g_att : A;
    const float* W = (mode == 3) ? W0 : (z == 0) ? W0 : (z == 1) ? W1 : W2;
    float* C = (mode == 3) ? Cext : (z == 0) ? g_q : (z == 1) ? g_k : g_v;

    auto load_chunk = [&](int k0, int bufi) {
#pragma unroll
        for (int i = 0; i < 4; i++) {
            int idx = t + i * 256;
            int row = idx >> 3;
            int fc  = (idx & 7) * 4;
            cp16(smem_u32(&As[bufi][row][fc]), Asrc + (size_t)(m0 + row) * 1024 + k0 + fc);
            cp16(smem_u32(&Ws[bufi][row][fc]), W + (size_t)(n0 + row) * 1024 + k0 + fc);
        }
    };

    float c[2][8][4];
#pragma unroll
    for (int mi = 0; mi < 2; mi++)
#pragma unroll
        for (int ni = 0; ni < 8; ni++)
#pragma unroll
            for (int e = 0; e < 4; e++) c[mi][ni][e] = 0.f;

    load_chunk(0, 0);  CP_COMMIT();
    load_chunk(32, 1); CP_COMMIT();

    for (int kc = 0; kc < 32; kc++) {
        CP_WAIT1();
        __syncthreads();
        const int bi = kc & 1;

#pragma unroll
        for (int kk = 0; kk < 4; kk++) {
            const int kb = kk * 8;
            unsigned ah[2][4], al[2][4], bh[8][2];
#pragma unroll
            for (int mi = 0; mi < 2; mi++) {
                const int rb = wm * 32 + mi * 16;
                split_tf32(As[bi][rb + g][kb + tg],          ah[mi][0], al[mi][0]);
                split_tf32(As[bi][rb + g + 8][kb + tg],      ah[mi][1], al[mi][1]);
                split_tf32(As[bi][rb + g][kb + tg + 4],      ah[mi][2], al[mi][2]);
                split_tf32(As[bi][rb + g + 8][kb + tg + 4],  ah[mi][3], al[mi][3]);
            }
#pragma unroll
            for (int ni = 0; ni < 8; ni++) {
                const int nb = wn * 64 + ni * 8;
                bh[ni][0] = f2tf32(Ws[bi][nb + g][kb + tg]);
                bh[ni][1] = f2tf32(Ws[bi][nb + g][kb + tg + 4]);
            }
#pragma unroll
            for (int mi = 0; mi < 2; mi++)
#pragma unroll
                for (int ni = 0; ni < 8; ni++) {
                    mma_tf32(c[mi][ni][0], c[mi][ni][1], c[mi][ni][2], c[mi][ni][3],
                             ah[mi][0], ah[mi][1], ah[mi][2], ah[mi][3],
                             bh[ni][0], bh[ni][1]);
                    mma_tf32(c[mi][ni][0], c[mi][ni][1], c[mi][ni][2], c[mi][ni][3],
                             al[mi][0], al[mi][1], al[mi][2], al[mi][3],
                             bh[ni][0], bh[ni][1]);
                }
        }

        __syncthreads();
        if (kc < 30) load_chunk((kc + 2) * 32, bi);
        CP_COMMIT();
    }

    // Epilogue: each c fragment element pair (c0,c1)/(c2,c3) is 2 contiguous n.
#pragma unroll
    for (int mi = 0; mi < 2; mi++) {
#pragma unroll
        for (int ni = 0; ni < 8; ni++) {
            int mA = m0 + wm * 32 + mi * 16 + g;
            int mB = mA + 8;
            int n  = n0 + wn * 64 + ni * 8 + 2 * tg;
            if (mode == 3) {
                float bx = bias[n], by = bias[n + 1];
                *(float2*)(C + (size_t)mA * 1024 + n) =
                    make_float2(c[mi][ni][0] + bx, c[mi][ni][1] + by);
                *(float2*)(C + (size_t)mB * 1024 + n) =
                    make_float2(c[mi][ni][2] + bx, c[mi][ni][3] + by);
            } else {
                int h  = n >> 6;
                int dh = n & 63;
                {
                    int b = mA >> 11, s = mA & 2047;
                    *(float2*)(C + (size_t)((b * HH + h) * SS + s) * DH + dh) =
                        make_float2(c[mi][ni][0], c[mi][ni][1]);
                }
                {
                    int b = mB >> 11, s = mB & 2047;
                    *(float2*)(C + (size_t)((b * HH + h) * SS + s) * DH + dh) =
                        make_float2(c[mi][ni][2], c[mi][ni][3]);
                }
            }
        }
    }
}

// ---------------------------------------------------------------------------
// Flash attention via tensor cores, cp.async double-buffered K/V tiles.
// Block = 64 query rows, 4 warps (16 rows each), 64-key tiles through SMEM.
// QK^T: single tf32 (RNA both sides, zero-mean error ~2e-4 on scores).
// P*V:  single bf16 m16n8k16 — S C-fragment IS the k16 A-fragment, so P
//       never leaves registers; V packed to bf16x2 at use.
// Reads g_q/g_k/g_v [B,H,S,Dh]; writes g_att [B,S,D].
// ---------------------------------------------------------------------------
__global__ void __launch_bounds__(128, 3) attn_mma() {
    const int b = blockIdx.z;
    const int h = blockIdx.y;
    const int t = threadIdx.x;
    const int warp = t >> 5;
    const int lane = t & 31;
    const int g  = lane >> 2;   // 0..7
    const int tg = lane & 3;    // 0..3
    const int qrow0 = blockIdx.x * 64 + warp * 16;
    const size_t bh = (size_t)(b * HH + h) * SS;

    __shared__ float Ks[2][64][68];   // fp32 K (4g+tg pattern conflict-free)
    __shared__ float Vs[2][64][68];   // fp32 V (8tg+g / 8tg+4+g conflict-free)

    auto load_kv = [&](int kt, int bufi) {
#pragma unroll
        for (int i = 0; i < 8; i++) {
            int idx = t + i * 128;
            int r = idx >> 4;
            int c = (idx & 15) * 4;
            cp16(smem_u32(&Ks[bufi][r][c]), g_k + (bh + kt + r) * DH + c);
            cp16(smem_u32(&Vs[bufi][r][c]), g_v + (bh + kt + r) * DH + c);
        }
    };

    // Q fragments (single tf32, pre-scaled 1/8).
    unsigned qh[8][4];
    {
        const float* Q = g_q + (bh + qrow0) * DH;
#pragma unroll
        for (int kb = 0; kb < 8; kb++) {
            qh[kb][0] = f2tf32(Q[g * DH + kb * 8 + tg] * 0.125f);
            qh[kb][1] = f2tf32(Q[(g + 8) * DH + kb * 8 + tg] * 0.125f);
            qh[kb][2] = f2tf32(Q[g * DH + kb * 8 + tg + 4] * 0.125f);
            qh[kb][3] = f2tf32(Q[(g + 8) * DH + kb * 8 + tg + 4] * 0.125f);
        }
    }

    float o[8][4];
#pragma unroll
    for (int ni = 0; ni < 8; ni++)
#pragma unroll
        for (int e = 0; e < 4; e++) o[ni][e] = 0.f;
    float mi0 = -1e30f, mi8 = -1e30f, li0 = 0.f, li8 = 0.f;

    load_kv(0, 0);  CP_COMMIT();
    load_kv(64, 1); CP_COMMIT();

    for (int it = 0; it < 32; it++) {
        CP_WAIT1();
        __syncthreads();
        const int bi = it & 1;

        // S = Q * K^T (single tf32), warp computes 16x64 scores.
        float s[8][4];
#pragma unroll
        for (int ni = 0; ni < 8; ni++)
#pragma unroll
            for (int e = 0; e < 4; e++) s[ni][e] = 0.f;

#pragma unroll
        for (int kb = 0; kb < 8; kb++) {
#pragma unroll
            for (int ni = 0; ni < 8; ni++) {
                unsigned b0h = f2tf32(Ks[bi][ni * 8 + g][kb * 8 + tg]);
                unsigned b1h = f2tf32(Ks[bi][ni * 8 + g][kb * 8 + tg + 4]);
                mma_tf32(s[ni][0], s[ni][1], s[ni][2], s[ni][3],
                         qh[kb][0], qh[kb][1], qh[kb][2], qh[kb][3], b0h, b1h);
            }
        }

        // Online softmax. Rows: g (elements 0,1) and g+8 (elements 2,3).
        float t0 = mi0, t8 = mi8;
#pragma unroll
        for (int ni = 0; ni < 8; ni++) {
            t0 = fmaxf(t0, fmaxf(s[ni][0], s[ni][1]));
            t8 = fmaxf(t8, fmaxf(s[ni][2], s[ni][3]));
        }
        t0 = fmaxf(t0, __shfl_xor_sync(0xffffffffu, t0, 1));
        t0 = fmaxf(t0, __shfl_xor_sync(0xffffffffu, t0, 2));
        t8 = fmaxf(t8, __shfl_xor_sync(0xffffffffu, t8, 1));
        t8 = fmaxf(t8, __shfl_xor_sync(0xffffffffu, t8, 2));

        float c0 = __expf(mi0 - t0);
        float c8 = __expf(mi8 - t8);
        mi0 = t0; mi8 = t8;
        li0 *= c0; li8 *= c8;

        float rs0 = 0.f, rs8 = 0.f;
#pragma unroll
        for (int ni = 0; ni < 8; ni++) {
            o[ni][0] *= c0; o[ni][1] *= c0;
            o[ni][2] *= c8; o[ni][3] *= c8;
            float p0 = __expf(s[ni][0] - mi0);
            float p1 = __expf(s[ni][1] - mi0);
            float p2 = __expf(s[ni][2] - mi8);
            float p3 = __expf(s[ni][3] - mi8);
            rs0 += p0 + p1;
            rs8 += p2 + p3;
            s[ni][0] = p0; s[ni][1] = p1; s[ni][2] = p2; s[ni][3] = p3;
        }
        li0 += rs0; li8 += rs8;

        // O += P * V (single bf16 m16n8k16). P stays in registers:
        // s C-fragment (rows g/g+8, cols 2tg,2tg+1 per ni) == k16 A-fragment.
#pragma unroll
        for (int kb = 0; kb < 4; kb++) {
            unsigned a0 = packbf(s[2 * kb][0],     s[2 * kb][1]);
            unsigned a1 = packbf(s[2 * kb][2],     s[2 * kb][3]);
            unsigned a2 = packbf(s[2 * kb + 1][0], s[2 * kb + 1][1]);
            unsigned a3 = packbf(s[2 * kb + 1][2], s[2 * kb + 1][3]);
#pragma unroll
            for (int ni = 0; ni < 8; ni++) {
                const int n = ni * 8 + g;
                unsigned b0 = packbf(Vs[bi][kb * 16 + 2 * tg][n],
                                     Vs[bi][kb * 16 + 2 * tg + 1][n]);
                unsigned b1 = packbf(Vs[bi][kb * 16 + 8 + 2 * tg][n],
                                     Vs[bi][kb * 16 + 9 + 2 * tg][n]);
                mma_bf16(o[ni][0], o[ni][1], o[ni][2], o[ni][3],
                         a0, a1, a2, a3, b0, b1);
            }
        }

        __syncthreads();
        if (it < 30) load_kv((it + 2) * 64, bi);
        CP_COMMIT();
    }

    li0 += __shfl_xor_sync(0xffffffffu, li0, 1);
    li0 += __shfl_xor_sync(0xffffffffu, li0, 2);
    li8 += __shfl_xor_sync(0xffffffffu, li8, 1);
    li8 += __shfl_xor_sync(0xffffffffu, li8, 2);
    float inv0 = 1.f / li0;
    float inv8 = 1.f / li8;

    float* O0 = g_att + ((size_t)b * SS + qrow0 + g) * DD + h * DH;
    float* O8 = g_att + ((size_t)b * SS + qrow0 + 8 + g) * DD + h * DH;
#pragma unroll
    for (int ni = 0; ni < 8; ni++) {
        *(float2*)(O0 + ni * 8 + 2 * tg) = make_float2(o[ni][0] * inv0, o[ni][1] * inv0);
        *(float2*)(O8 + ni * 8 + 2 * tg) = make_float2(o[ni][2] * inv8, o[ni][3] * inv8);
    }
}

extern "C" void kernel_launch(void* const* d_in, const int* in_sizes, int n_in,
                              void* d_out, int out_size) {
    const float* x  = (const float*)d_in[0];
    const float* wq = (const float*)d_in[1];
    const float* wk = (const float*)d_in[2];
    const float* wv = (const float*)d_in[3];
    const float* wo = (const float*)d_in[4];
    const float* bo = (const float*)d_in[5];
    float* out = (float*)d_out;

    dim3 gqkv(DD / 128, MM / 128, 3);   // (8, 32, 3) fused Q/K/V projections
    gemm_tf32<<<gqkv, 256>>>(x, wq, wk, wv, nullptr, nullptr, 0);

    dim3 ga(SS / 64, HH, BB);           // (32, 16, 2)
    attn_mma<<<ga, 128>>>();

    dim3 go(DD / 128, MM / 128, 1);
    gemm_tf32<<<go, 256>>>(nullptr, wo, nullptr, nullptr, bo, out, 3);
}